// round 15
// baseline (speedup 1.0000x reference)
#include <cuda_runtime.h>
#include <cuda_fp16.h>
#include <math.h>
#include <stdint.h>

#define B_   2
#define L_   4096
#define C_   1024
#define H_   16
#define D_   64
#define WIN_ 128
#define NB_  (L_ / WIN_)
#define M_   (B_ * L_)   // 8192 rows
#define NQKV 3072
#define MHALF 4096

// ---------------- scratch (device globals; no allocation allowed) ----------
__device__ __half g_qkv[(size_t)M_ * NQKV];
__device__ __half g_att[(size_t)M_ * C_];
__device__ __half g_xh [(size_t)M_ * C_];
__device__ __half g_wt [4][(size_t)C_ * C_];   // [N][K] fp16, wq|wk|wv|wo
__device__ float  g_b3 [NQKV];

// ---------------------------------------------------------------------------
// helpers
// ---------------------------------------------------------------------------
__device__ __forceinline__ uint32_t smem_u32(const void* p) {
    uint32_t a;
    asm("{ .reg .u64 t; cvta.to.shared.u64 t, %1; cvt.u32.u64 %0, t; }"
        : "=r"(a) : "l"(p));
    return a;
}
__device__ __forceinline__ void cp_async16(uint32_t dst, const void* src) {
    asm volatile("cp.async.cg.shared.global [%0], [%1], 16;"
                 :: "r"(dst), "l"(src) : "memory");
}
__device__ __forceinline__ void cp_async16z(uint32_t dst, const void* src, unsigned sz) {
    asm volatile("cp.async.cg.shared.global [%0], [%1], 16, %2;"
                 :: "r"(dst), "l"(src), "r"(sz) : "memory");
}
__device__ __forceinline__ void cp_commit() {
    asm volatile("cp.async.commit_group;" ::: "memory");
}
__device__ __forceinline__ void mma_f16_16x8x16(float c[4], const uint32_t a[4],
                                                uint32_t b0, uint32_t b1) {
    asm volatile(
        "mma.sync.aligned.m16n8k16.row.col.f32.f16.f16.f32 "
        "{%0,%1,%2,%3}, {%4,%5,%6,%7}, {%8,%9}, {%0,%1,%2,%3};"
        : "+f"(c[0]), "+f"(c[1]), "+f"(c[2]), "+f"(c[3])
        : "r"(a[0]), "r"(a[1]), "r"(a[2]), "r"(a[3]), "r"(b0), "r"(b1));
}
__device__ __forceinline__ void ldsm_x4(uint32_t (&r)[4], uint32_t addr) {
    asm volatile("ldmatrix.sync.aligned.m8n8.x4.shared.b16 {%0,%1,%2,%3}, [%4];"
                 : "=r"(r[0]), "=r"(r[1]), "=r"(r[2]), "=r"(r[3]) : "r"(addr));
}
__device__ __forceinline__ void ldsm_x4_t(uint32_t (&r)[4], uint32_t addr) {
    asm volatile("ldmatrix.sync.aligned.m8n8.x4.trans.shared.b16 {%0,%1,%2,%3}, [%4];"
                 : "=r"(r[0]), "=r"(r[1]), "=r"(r[2]), "=r"(r[3]) : "r"(addr));
}

// ---------------------------------------------------------------------------
// transpose one 32x32 fp32 tile -> fp16 [N][K]
// ---------------------------------------------------------------------------
__device__ __forceinline__ void transpose_tile(const float* __restrict__ W,
                                               __half* __restrict__ Wt,
                                               int t, int tid)
{
    __shared__ float tile[32][33];
    int tx = tid & 31, ty = tid >> 5;
    int bx = t & 31, by = t >> 5;
    int xcol = bx * 32 + tx;
    int yrow = by * 32 + ty;
    #pragma unroll
    for (int dy = 0; dy < 32; dy += 8)
        tile[ty + dy][tx] = W[(size_t)(yrow + dy) * C_ + xcol];
    __syncthreads();
    int nx = by * 32 + tx;
    int ny = bx * 32 + ty;
    #pragma unroll
    for (int dy = 0; dy < 32; dy += 8)
        Wt[(size_t)(ny + dy) * C_ + nx] = __float2half_rn(tile[tx][ty + dy]);
}

// prep0 (critical path): x batch0 -> fp16 (4096 blks), wq/wk/wv (3072), bias (4)
__global__ __launch_bounds__(256)
void prep0_kernel(const float* __restrict__ x,
                  const float* __restrict__ wq, const float* __restrict__ wk,
                  const float* __restrict__ wv,
                  const float* __restrict__ bq, const float* __restrict__ bk,
                  const float* __restrict__ bv,
                  __half* __restrict__ xh, __half* __restrict__ wt,
                  float* __restrict__ b3)
{
    const int bid = blockIdx.x, tid = threadIdx.x;
    if (bid < 4096) {
        size_t i = ((size_t)bid * 256 + tid) * 4;
        float4 v = *(const float4*)(x + i);
        __half2* o = (__half2*)(xh + i);
        o[0] = __floats2half2_rn(v.x, v.y);
        o[1] = __floats2half2_rn(v.z, v.w);
    } else if (bid < 7168) {
        int which = (bid - 4096) >> 10;
        int t     = (bid - 4096) & 1023;
        const float* W = (which == 0) ? wq : (which == 1) ? wk : wv;
        transpose_tile(W, wt + (size_t)which * C_ * C_, t, tid);
    } else {
        int i = (bid - 7168) * 256 + tid;
        b3[i]           = bq[i];
        b3[i + C_]      = bk[i];
        b3[i + 2 * C_]  = bv[i];
    }
}

// side stream: x batch1 -> fp16 (4096 blocks); x/xh pre-offset to batch 1
__global__ __launch_bounds__(256)
void prep_x1_kernel(const float* __restrict__ x, __half* __restrict__ xh)
{
    size_t i = ((size_t)blockIdx.x * 256 + threadIdx.x) * 4;
    float4 v = *(const float4*)(x + i);
    __half2* o = (__half2*)(xh + i);
    o[0] = __floats2half2_rn(v.x, v.y);
    o[1] = __floats2half2_rn(v.z, v.w);
}

// side stream: wo transpose (1024 blocks)
__global__ __launch_bounds__(256)
void prep_wo_kernel(const float* __restrict__ wo, __half* __restrict__ wto)
{
    transpose_tile(wo, wto, blockIdx.x, threadIdx.x);
}

// ---------------------------------------------------------------------------
// fp16 mma.sync GEMM: 128x256 CTA, 16 warps (4M x 4N), warp 32x64, BK=64,
//   3 stages, fp32 accumulate.
// ---------------------------------------------------------------------------
#define GBM 128
#define GBN 256
#define GBK 64
#define GSTG 3
#define GROWB 144
#define GST_BYTES ((GBM + GBN) * GROWB)       // 55296
#define GSMEM_BYTES (GSTG * GST_BYTES)        // 165888
#define GNT (C_ / GBK)                        // 16
#define GTHREADS 512

__device__ __forceinline__ void g_load_stage(const __half* __restrict__ A,
                                             const __half* __restrict__ Wt,
                                             int row0, int col0, int kt,
                                             uint32_t sstage, int tid)
{
    const int kf = kt * GBK;
    uint32_t aBase = sstage;
    uint32_t bBase = sstage + GBM * GROWB;
    #pragma unroll
    for (int it = 0; it < 6; it++) {
        int i = tid + it * GTHREADS;
        if (i < GBM * 8) {
            int r = i >> 3, c = i & 7;
            cp_async16(aBase + r * GROWB + c * 16,
                       A + (size_t)(row0 + r) * C_ + kf + c * 8);
        } else {
            int j = i - GBM * 8;
            int n = j >> 3, c = j & 7;
            cp_async16(bBase + n * GROWB + c * 16,
                       Wt + (size_t)(col0 + n) * C_ + kf + c * 8);
        }
    }
    cp_commit();
}

template<bool HALF_OUT>
__global__ __launch_bounds__(GTHREADS, 1)
void gemm_f16_kernel(const __half* __restrict__ A,
                     const __half* __restrict__ Wt,
                     const float* __restrict__ bias,
                     void* __restrict__ Cm,
                     int NS)
{
    extern __shared__ char sm[];
    const int tid    = threadIdx.x;
    const int lane   = tid & 31;
    const int wid    = tid >> 5;
    const int warp_m = wid & 3;
    const int warp_n = wid >> 2;
    const int grp    = lane >> 2;
    const int tig    = lane & 3;
    const int row0   = blockIdx.y * GBM;
    const int col0   = blockIdx.x * GBN;

    const uint32_t sbase = smem_u32(sm);

    const uint32_t aoff = (warp_m * 32 + (lane & 15)) * GROWB
                        + ((lane >> 4) & 1) * 16;
    const uint32_t boff = (uint32_t)(GBM * GROWB)
                        + (warp_n * 64 + (lane & 7) + ((lane >> 4) & 1) * 8) * GROWB
                        + ((lane >> 3) & 1) * 16;

    float cf[2][8][4];
    #pragma unroll
    for (int mt = 0; mt < 2; mt++)
        #pragma unroll
        for (int nt = 0; nt < 8; nt++)
            #pragma unroll
            for (int r = 0; r < 4; r++)
                cf[mt][nt][r] = 0.0f;

    #pragma unroll
    for (int s = 0; s < GSTG - 1; s++)
        g_load_stage(A, Wt, row0, col0, s, sbase + s * GST_BYTES, tid);

    for (int t = 0; t < GNT; t++) {
        asm volatile("cp.async.wait_group %0;" :: "n"(GSTG - 2));
        __syncthreads();

        int j = t + GSTG - 1;
        if (j < GNT)
            g_load_stage(A, Wt, row0, col0, j,
                         sbase + (j % GSTG) * GST_BYTES, tid);
        else
            cp_commit();

        const uint32_t stg = sbase + (t % GSTG) * GST_BYTES;

        #pragma unroll
        for (int ks = 0; ks < 4; ks++) {
            const uint32_t kb = ks * 32;
            uint32_t a0[4], a1[4];
            ldsm_x4(a0, stg + aoff + kb);
            ldsm_x4(a1, stg + aoff + 16 * GROWB + kb);
            #pragma unroll
            for (int np = 0; np < 4; np++) {
                uint32_t bb[4];
                ldsm_x4(bb, stg + boff + np * (16 * GROWB) + kb);
                mma_f16_16x8x16(cf[0][2 * np],     a0, bb[0], bb[1]);
                mma_f16_16x8x16(cf[1][2 * np],     a1, bb[0], bb[1]);
                mma_f16_16x8x16(cf[0][2 * np + 1], a0, bb[2], bb[3]);
                mma_f16_16x8x16(cf[1][2 * np + 1], a1, bb[2], bb[3]);
            }
        }
    }

    #pragma unroll
    for (int mt = 0; mt < 2; mt++) {
        int rbase = row0 + warp_m * 32 + mt * 16 + grp;
        #pragma unroll
        for (int nt = 0; nt < 8; nt++) {
            int col = col0 + warp_n * 64 + nt * 8 + tig * 2;
            float2 b2 = *(const float2*)(bias + col);
            if (HALF_OUT) {
                __half2* o = (__half2*)Cm;
                o[((size_t)rbase * NS + col) / 2] =
                    __floats2half2_rn(cf[mt][nt][0] + b2.x, cf[mt][nt][1] + b2.y);
                o[((size_t)(rbase + 8) * NS + col) / 2] =
                    __floats2half2_rn(cf[mt][nt][2] + b2.x, cf[mt][nt][3] + b2.y);
            } else {
                float* o = (float*)Cm;
                float2 o0, o1;
                o0.x = cf[mt][nt][0] + b2.x;  o0.y = cf[mt][nt][1] + b2.y;
                o1.x = cf[mt][nt][2] + b2.x;  o1.y = cf[mt][nt][3] + b2.y;
                *(float2*)(o + (size_t)rbase * NS + col)       = o0;
                *(float2*)(o + (size_t)(rbase + 8) * NS + col) = o1;
            }
        }
    }
}

// ---------------------------------------------------------------------------
// fp16 tensor-core flash attention (2 CTAs/SM, per-batch launch)
// ---------------------------------------------------------------------------
#define AROWB 144
#define AQB   (128 * AROWB)
#define AKVB  (2 * 128 * AROWB)
#define ASM_BYTES (AQB + 2 * AKVB)     // 92160

template<int CI>
__device__ __forceinline__ void attn_chunk(
    uint32_t qb, uint32_t kb, uint32_t vb,
    int r0, int lane, int grp, int tig, int lo, int hi,
    float (&oc)[8][4], float& m0, float& m1, float& l0, float& l1)
{
    float scr[16][4];
    #pragma unroll
    for (int nt = 0; nt < 16; nt++)
        #pragma unroll
        for (int e = 0; e < 4; e++) scr[nt][e] = 0.f;

    const uint32_t qoff = qb + (r0 + (lane & 15)) * AROWB + ((lane >> 4) & 1) * 16;
    const uint32_t koff = kb + ((lane & 7) + ((lane >> 4) & 1) * 8) * AROWB
                        + ((lane >> 3) & 1) * 16;

    #pragma unroll
    for (int ks = 0; ks < 4; ks++) {
        uint32_t qa[4];
        ldsm_x4(qa, qoff + ks * 32);
        #pragma unroll
        for (int np = 0; np < 8; np++) {
            if (np < lo / 2 || np >= hi / 2) continue;
            uint32_t bb[4];
            ldsm_x4(bb, koff + np * (16 * AROWB) + ks * 32);
            mma_f16_16x8x16(scr[2 * np],     qa, bb[0], bb[1]);
            mma_f16_16x8x16(scr[2 * np + 1], qa, bb[2], bb[3]);
        }
    }
    #pragma unroll
    for (int nt = 0; nt < 16; nt++) {
        if (nt < lo || nt >= hi) continue;
        #pragma unroll
        for (int e = 0; e < 4; e++) scr[nt][e] *= 0.125f;
    }

    const int ra = r0 + grp, rb = ra + 8;
    if (CI == 0) {
        #pragma unroll
        for (int nt = 0; nt < 16; nt++) {
            if (nt < lo || nt >= hi) continue;
            int c = nt * 8 + 2 * tig;
            if (c     < ra) scr[nt][0] = -INFINITY;
            if (c + 1 < ra) scr[nt][1] = -INFINITY;
            if (c     < rb) scr[nt][2] = -INFINITY;
            if (c + 1 < rb) scr[nt][3] = -INFINITY;
        }
    }
    if (CI == 2) {
        #pragma unroll
        for (int nt = 0; nt < 16; nt++) {
            if (nt < lo || nt >= hi) continue;
            int c = nt * 8 + 2 * tig;
            if (c     > ra) scr[nt][0] = -INFINITY;
            if (c + 1 > ra) scr[nt][1] = -INFINITY;
            if (c     > rb) scr[nt][2] = -INFINITY;
            if (c + 1 > rb) scr[nt][3] = -INFINITY;
        }
    }

    float mx0 = -INFINITY, mx1 = -INFINITY;
    #pragma unroll
    for (int nt = 0; nt < 16; nt++) {
        if (nt < lo || nt >= hi) continue;
        mx0 = fmaxf(mx0, fmaxf(scr[nt][0], scr[nt][1]));
        mx1 = fmaxf(mx1, fmaxf(scr[nt][2], scr[nt][3]));
    }
    mx0 = fmaxf(mx0, __shfl_xor_sync(0xffffffffu, mx0, 1));
    mx0 = fmaxf(mx0, __shfl_xor_sync(0xffffffffu, mx0, 2));
    mx1 = fmaxf(mx1, __shfl_xor_sync(0xffffffffu, mx1, 1));
    mx1 = fmaxf(mx1, __shfl_xor_sync(0xffffffffu, mx1, 2));

    float mn0 = fmaxf(m0, mx0), mn1 = fmaxf(m1, mx1);
    float cr0 = __expf(m0 - mn0), cr1 = __expf(m1 - mn1);
    m0 = mn0; m1 = mn1;
    l0 *= cr0; l1 *= cr1;
    #pragma unroll
    for (int nt = 0; nt < 8; nt++) {
        oc[nt][0] *= cr0; oc[nt][1] *= cr0;
        oc[nt][2] *= cr1; oc[nt][3] *= cr1;
    }

    #pragma unroll
    for (int nt = 0; nt < 16; nt++) {
        if (nt < lo || nt >= hi) continue;
        float p0 = __expf(scr[nt][0] - mn0);
        float p1 = __expf(scr[nt][1] - mn0);
        float p2 = __expf(scr[nt][2] - mn1);
        float p3 = __expf(scr[nt][3] - mn1);
        __half2 h01 = __floats2half2_rn(p0, p1);
        __half2 h23 = __floats2half2_rn(p2, p3);
        float2 f01 = __half22float2(h01);
        float2 f23 = __half22float2(h23);
        l0 += f01.x + f01.y;
        l1 += f23.x + f23.y;
        scr[nt][0] = __uint_as_float(*reinterpret_cast<uint32_t*>(&h01));
        scr[nt][1] = __uint_as_float(*reinterpret_cast<uint32_t*>(&h23));
    }

    const uint32_t voffb = vb + (lane & 15) * AROWB + ((lane >> 4) & 1) * 16;
    #pragma unroll
    for (int j = 0; j < 8; j++) {
        if (j < lo / 2 || j >= hi / 2) continue;
        uint32_t pa[4];
        pa[0] = __float_as_uint(scr[2 * j][0]);
        pa[1] = __float_as_uint(scr[2 * j][1]);
        pa[2] = __float_as_uint(scr[2 * j + 1][0]);
        pa[3] = __float_as_uint(scr[2 * j + 1][1]);
        const uint32_t vrow = voffb + j * (16 * AROWB);
        #pragma unroll
        for (int dp = 0; dp < 4; dp++) {
            uint32_t bb[4];
            ldsm_x4_t(bb, vrow + dp * 32);
            mma_f16_16x8x16(oc[2 * dp],     pa, bb[0], bb[1]);
            mma_f16_16x8x16(oc[2 * dp + 1], pa, bb[2], bb[3]);
        }
    }
}

// qkv/att pointers pre-offset to the batch; grid = (NB_, H_, 1)
__global__ __launch_bounds__(256, 2)
void attn_mma_kernel(const __half* __restrict__ qkv,
                     __half* __restrict__ att)
{
    extern __shared__ char sm[];
    const int blk = blockIdx.x, h = blockIdx.y;
    const int tid = threadIdx.x, lane = tid & 31, wid = tid >> 5;
    const int grp = lane >> 2, tig = lane & 3;
    const int r0 = wid * 16;
    const size_t rowbase = (size_t)blk * WIN_;

    const uint32_t qb = smem_u32(sm);
    const uint32_t kv0 = qb + AQB;

    const __half* q = qkv;
    const __half* k = qkv + C_;
    const __half* v = qkv + 2 * C_;

    #pragma unroll
    for (int it = 0; it < 4; it++) {
        int i = tid + it * 256;
        int r = i >> 3, c = i & 7;
        cp_async16(qb + r * AROWB + c * 16,
                   q + (rowbase + r) * NQKV + h * D_ + c * 8);
    }

    auto stage = [&](int ci, int buf) {
        uint32_t kd = kv0 + buf * AKVB;
        uint32_t vd = kd + 128 * AROWB;
        int base = (blk + ci - 1) * WIN_;
        #pragma unroll
        for (int it = 0; it < 8; it++) {
            int i = tid + it * 256;
            int isV = (i >= 1024);
            int ii = i & 1023;
            int r = ii >> 3, c = ii & 7;
            int pos = base + r;
            unsigned sz = (pos >= 0 && pos < L_) ? 16u : 0u;
            int posc = pos < 0 ? 0 : (pos >= L_ ? L_ - 1 : pos);
            const __half* src = (isV ? v : k) + (size_t)posc * NQKV + h * D_ + c * 8;
            uint32_t dst = (isV ? vd : kd) + r * AROWB + c * 16;
            cp_async16z(dst, src, sz);
        }
        cp_commit();
    };

    stage(0, 0);
    stage(1, 1);

    float oc[8][4];
    #pragma unroll
    for (int nt = 0; nt < 8; nt++)
        #pragma unroll
        for (int e = 0; e < 4; e++) oc[nt][e] = 0.f;
    float m0 = -INFINITY, m1 = -INFINITY, l0 = 0.f, l1 = 0.f;

    asm volatile("cp.async.wait_group 1;" ::: "memory");
    __syncthreads();
    attn_chunk<0>(qb, kv0, kv0 + 128 * AROWB, r0, lane, grp, tig,
                  2 * wid, 16, oc, m0, m1, l0, l1);
    __syncthreads();
    stage(2, 0);
    asm volatile("cp.async.wait_group 1;" ::: "memory");
    __syncthreads();
    attn_chunk<1>(qb, kv0 + AKVB, kv0 + AKVB + 128 * AROWB, r0, lane, grp, tig,
                  0, 16, oc, m0, m1, l0, l1);
    asm volatile("cp.async.wait_group 0;" ::: "memory");
    __syncthreads();
    attn_chunk<2>(qb, kv0, kv0 + 128 * AROWB, r0, lane, grp, tig,
                  0, 2 * wid + 2, oc, m0, m1, l0, l1);

    l0 += __shfl_xor_sync(0xffffffffu, l0, 1);
    l0 += __shfl_xor_sync(0xffffffffu, l0, 2);
    l1 += __shfl_xor_sync(0xffffffffu, l1, 1);
    l1 += __shfl_xor_sync(0xffffffffu, l1, 2);
    float i0 = 1.0f / l0, i1 = 1.0f / l1;

    size_t oa = (rowbase + r0 + grp) * C_ + h * D_;
    size_t ob = oa + 8 * C_;
    __half2* o2 = (__half2*)att;
    #pragma unroll
    for (int nt = 0; nt < 8; nt++) {
        o2[(oa + nt * 8 + tig * 2) / 2] =
            __floats2half2_rn(oc[nt][0] * i0, oc[nt][1] * i0);
        o2[(ob + nt * 8 + tig * 2) / 2] =
            __floats2half2_rn(oc[nt][2] * i1, oc[nt][3] * i1);
    }
}

// ---------------------------------------------------------------------------
extern "C" void kernel_launch(void* const* d_in, const int* in_sizes, int n_in,
                              void* d_out, int out_size)
{
    const float* x  = (const float*)d_in[0];
    const float* wq = (const float*)d_in[1];
    const float* bq = (const float*)d_in[2];
    const float* wk = (const float*)d_in[3];
    const float* bk = (const float*)d_in[4];
    const float* wv = (const float*)d_in[5];
    const float* bv = (const float*)d_in[6];
    const float* wo = (const float*)d_in[7];
    const float* bo = (const float*)d_in[8];
    float* out = (float*)d_out;

    __half *qkv, *att, *xh, *wt;
    float *b3;
    cudaGetSymbolAddress((void**)&qkv, g_qkv);
    cudaGetSymbolAddress((void**)&att, g_att);
    cudaGetSymbolAddress((void**)&xh,  g_xh);
    cudaGetSymbolAddress((void**)&wt,  g_wt);
    cudaGetSymbolAddress((void**)&b3,  g_b3);
    __half* wtq = wt;
    __half* wto = wt + 3 * (size_t)C_ * C_;

    // one-time host objects (identical captured graph each call)
    static cudaStream_t s1 = nullptr;
    static cudaEvent_t evRoot, evP1, evQ0, evWo0;
    if (!s1) {
        cudaStreamCreateWithFlags(&s1, cudaStreamNonBlocking);
        cudaEventCreateWithFlags(&evRoot, cudaEventDisableTiming);
        cudaEventCreateWithFlags(&evP1,   cudaEventDisableTiming);
        cudaEventCreateWithFlags(&evQ0,   cudaEventDisableTiming);
        cudaEventCreateWithFlags(&evWo0,  cudaEventDisableTiming);
    }

    cudaFuncSetAttribute(gemm_f16_kernel<true>,
                         cudaFuncAttributeMaxDynamicSharedMemorySize, GSMEM_BYTES);
    cudaFuncSetAttribute(gemm_f16_kernel<false>,
                         cudaFuncAttributeMaxDynamicSharedMemorySize, GSMEM_BYTES);
    cudaFuncSetAttribute(attn_mma_kernel,
                         cudaFuncAttributeMaxDynamicSharedMemorySize, ASM_BYTES);

    // fork side stream
    cudaEventRecord(evRoot, 0);
    cudaStreamWaitEvent(s1, evRoot, 0);

    // s1: wo transpose + batch-1 x conversion (overlaps prep0 + qkv0)
    prep_wo_kernel<<<1024, 256, 0, s1>>>(wo, wto);
    prep_x1_kernel<<<4096, 256, 0, s1>>>(x + (size_t)MHALF * C_,
                                         xh + (size_t)MHALF * C_);
    cudaEventRecord(evP1, s1);

    // s0: critical prep (batch-0 x + qkv weights + bias), then QKV batch 0
    prep0_kernel<<<7172, 256>>>(x, wq, wk, wv, bq, bk, bv, xh, wt, b3);

    dim3 qkvGrid(NQKV / GBN, MHALF / GBM);   // (12, 32)
    gemm_f16_kernel<true><<<qkvGrid, GTHREADS, GSMEM_BYTES>>>(
        xh, wtq, b3, qkv, NQKV);
    cudaEventRecord(evQ0, 0);

    // s0: QKV batch 1 (needs prep_x1)
    cudaStreamWaitEvent(0, evP1, 0);
    gemm_f16_kernel<true><<<qkvGrid, GTHREADS, GSMEM_BYTES>>>(
        xh + (size_t)MHALF * C_, wtq, b3, qkv + (size_t)MHALF * NQKV, NQKV);

    // s1: attention batch 0 (after qkv0), then wo batch 0
    cudaStreamWaitEvent(s1, evQ0, 0);
    dim3 aGrid(NB_, H_, 1);
    attn_mma_kernel<<<aGrid, 256, ASM_BYTES, s1>>>(qkv, att);
    dim3 oGrid(C_ / GBN, MHALF / GBM);       // (4, 32)
    gemm_f16_kernel<false><<<oGrid, GTHREADS, GSMEM_BYTES, s1>>>(
        att, wto, bo, out, C_);
    cudaEventRecord(evWo0, s1);

    // s0: attention batch 1, join, wo batch 1
    attn_mma_kernel<<<aGrid, 256, ASM_BYTES>>>(
        qkv + (size_t)MHALF * NQKV, att + (size_t)MHALF * C_);
    cudaStreamWaitEvent(0, evWo0, 0);
    gemm_f16_kernel<false><<<oGrid, GTHREADS, GSMEM_BYTES>>>(
        att + (size_t)MHALF * C_, wto, bo, out + (size_t)MHALF * C_, C_);
}

// round 16
// speedup vs baseline: 1.0309x; 1.0309x over previous
#include <cuda_runtime.h>
#include <cuda_fp16.h>
#include <math.h>
#include <stdint.h>

#define B_   2
#define L_   4096
#define C_   1024
#define H_   16
#define D_   64
#define WIN_ 128
#define NB_  (L_ / WIN_)
#define M_   (B_ * L_)   // 8192 rows
#define NQKV 3072
#define MHALF 4096

// ---------------- scratch (device globals; no allocation allowed) ----------
__device__ __half g_qkv[(size_t)M_ * NQKV];
__device__ __half g_att[(size_t)M_ * C_];
__device__ __half g_xh [(size_t)M_ * C_];
__device__ __half g_wt [4][(size_t)C_ * C_];   // [N][K] fp16, wq|wk|wv|wo
__device__ float  g_b3 [NQKV];

// ---------------------------------------------------------------------------
// helpers
// ---------------------------------------------------------------------------
__device__ __forceinline__ uint32_t smem_u32(const void* p) {
    uint32_t a;
    asm("{ .reg .u64 t; cvta.to.shared.u64 t, %1; cvt.u32.u64 %0, t; }"
        : "=r"(a) : "l"(p));
    return a;
}
__device__ __forceinline__ void cp_async16(uint32_t dst, const void* src) {
    asm volatile("cp.async.cg.shared.global [%0], [%1], 16;"
                 :: "r"(dst), "l"(src) : "memory");
}
__device__ __forceinline__ void cp_async16z(uint32_t dst, const void* src, unsigned sz) {
    asm volatile("cp.async.cg.shared.global [%0], [%1], 16, %2;"
                 :: "r"(dst), "l"(src), "r"(sz) : "memory");
}
__device__ __forceinline__ void cp_commit() {
    asm volatile("cp.async.commit_group;" ::: "memory");
}
__device__ __forceinline__ void mma_f16_16x8x16(float c[4], const uint32_t a[4],
                                                uint32_t b0, uint32_t b1) {
    asm volatile(
        "mma.sync.aligned.m16n8k16.row.col.f32.f16.f16.f32 "
        "{%0,%1,%2,%3}, {%4,%5,%6,%7}, {%8,%9}, {%0,%1,%2,%3};"
        : "+f"(c[0]), "+f"(c[1]), "+f"(c[2]), "+f"(c[3])
        : "r"(a[0]), "r"(a[1]), "r"(a[2]), "r"(a[3]), "r"(b0), "r"(b1));
}
__device__ __forceinline__ void ldsm_x4(uint32_t (&r)[4], uint32_t addr) {
    asm volatile("ldmatrix.sync.aligned.m8n8.x4.shared.b16 {%0,%1,%2,%3}, [%4];"
                 : "=r"(r[0]), "=r"(r[1]), "=r"(r[2]), "=r"(r[3]) : "r"(addr));
}
__device__ __forceinline__ void ldsm_x4_t(uint32_t (&r)[4], uint32_t addr) {
    asm volatile("ldmatrix.sync.aligned.m8n8.x4.trans.shared.b16 {%0,%1,%2,%3}, [%4];"
                 : "=r"(r[0]), "=r"(r[1]), "=r"(r[2]), "=r"(r[3]) : "r"(addr));
}

// ---------------------------------------------------------------------------
// transpose one 32x32 fp32 tile -> fp16 [N][K]
// ---------------------------------------------------------------------------
__device__ __forceinline__ void transpose_tile(const float* __restrict__ W,
                                               __half* __restrict__ Wt,
                                               int t, int tid)
{
    __shared__ float tile[32][33];
    int tx = tid & 31, ty = tid >> 5;
    int bx = t & 31, by = t >> 5;
    int xcol = bx * 32 + tx;
    int yrow = by * 32 + ty;
    #pragma unroll
    for (int dy = 0; dy < 32; dy += 8)
        tile[ty + dy][tx] = W[(size_t)(yrow + dy) * C_ + xcol];
    __syncthreads();
    int nx = by * 32 + tx;
    int ny = bx * 32 + ty;
    #pragma unroll
    for (int dy = 0; dy < 32; dy += 8)
        Wt[(size_t)(ny + dy) * C_ + nx] = __float2half_rn(tile[tx][ty + dy]);
}

// prep_main: x -> fp16 (8192 blks), wq/wk/wv transpose (3072 blks), bias (4)
__global__ __launch_bounds__(256)
void prep_main_kernel(const float* __restrict__ x,
                      const float* __restrict__ wq, const float* __restrict__ wk,
                      const float* __restrict__ wv,
                      const float* __restrict__ bq, const float* __restrict__ bk,
                      const float* __restrict__ bv,
                      __half* __restrict__ xh, __half* __restrict__ wt,
                      float* __restrict__ b3)
{
    const int bid = blockIdx.x, tid = threadIdx.x;
    if (bid < 8192) {
        size_t i = ((size_t)bid * 256 + tid) * 4;
        float4 v = *(const float4*)(x + i);
        __half2* o = (__half2*)(xh + i);
        o[0] = __floats2half2_rn(v.x, v.y);
        o[1] = __floats2half2_rn(v.z, v.w);
    } else if (bid < 11264) {
        int which = (bid - 8192) >> 10;
        int t     = (bid - 8192) & 1023;
        const float* W = (which == 0) ? wq : (which == 1) ? wk : wv;
        transpose_tile(W, wt + (size_t)which * C_ * C_, t, tid);
    } else {
        int i = (bid - 11264) * 256 + tid;
        b3[i]           = bq[i];
        b3[i + C_]      = bk[i];
        b3[i + 2 * C_]  = bv[i];
    }
}

// prep_wo: wo transpose only (1024 blocks) — side stream
__global__ __launch_bounds__(256)
void prep_wo_kernel(const float* __restrict__ wo, __half* __restrict__ wto)
{
    transpose_tile(wo, wto, blockIdx.x, threadIdx.x);
}

// ---------------------------------------------------------------------------
// fp16 mma.sync GEMM: 128x128 CTA, 8 warps (4M x 2N), warp 32x64, BK=64,
//   3 stages, 2 CTAs/SM, fp32 accumulate.
// ---------------------------------------------------------------------------
#define GBM 128
#define GBN 128
#define GBK 64
#define GSTG 3
#define GROWB 144
#define GST_BYTES ((GBM + GBN) * GROWB)       // 36864
#define GSMEM_BYTES (GSTG * GST_BYTES)        // 110592
#define GNT (C_ / GBK)                        // 16
#define GTHREADS 256

__device__ __forceinline__ void g_load_stage(const __half* __restrict__ A,
                                             const __half* __restrict__ Wt,
                                             int row0, int col0, int kt,
                                             uint32_t sstage, int tid)
{
    const int kf = kt * GBK;
    uint32_t aBase = sstage;
    uint32_t bBase = sstage + GBM * GROWB;
    #pragma unroll
    for (int it = 0; it < 8; it++) {
        int i = tid + it * GTHREADS;          // 0..2047
        if (i < GBM * 8) {
            int r = i >> 3, c = i & 7;
            cp_async16(aBase + r * GROWB + c * 16,
                       A + (size_t)(row0 + r) * C_ + kf + c * 8);
        } else {
            int j = i - GBM * 8;
            int n = j >> 3, c = j & 7;
            cp_async16(bBase + n * GROWB + c * 16,
                       Wt + (size_t)(col0 + n) * C_ + kf + c * 8);
        }
    }
    cp_commit();
}

template<bool HALF_OUT>
__global__ __launch_bounds__(GTHREADS, 2)
void gemm_f16_kernel(const __half* __restrict__ A,
                     const __half* __restrict__ Wt,
                     const float* __restrict__ bias,
                     void* __restrict__ Cm,
                     int NS)
{
    extern __shared__ char sm[];
    const int tid    = threadIdx.x;
    const int lane   = tid & 31;
    const int wid    = tid >> 5;
    const int warp_m = wid & 3;                 // 0..3 -> 32-row slab
    const int warp_n = wid >> 2;                // 0..1 -> 64-col slab
    const int grp    = lane >> 2;
    const int tig    = lane & 3;
    const int row0   = blockIdx.y * GBM;
    const int col0   = blockIdx.x * GBN;

    const uint32_t sbase = smem_u32(sm);

    const uint32_t aoff = (warp_m * 32 + (lane & 15)) * GROWB
                        + ((lane >> 4) & 1) * 16;
    const uint32_t boff = (uint32_t)(GBM * GROWB)
                        + (warp_n * 64 + (lane & 7) + ((lane >> 4) & 1) * 8) * GROWB
                        + ((lane >> 3) & 1) * 16;

    float cf[2][8][4];
    #pragma unroll
    for (int mt = 0; mt < 2; mt++)
        #pragma unroll
        for (int nt = 0; nt < 8; nt++)
            #pragma unroll
            for (int r = 0; r < 4; r++)
                cf[mt][nt][r] = 0.0f;

    #pragma unroll
    for (int s = 0; s < GSTG - 1; s++)
        g_load_stage(A, Wt, row0, col0, s, sbase + s * GST_BYTES, tid);

    for (int t = 0; t < GNT; t++) {
        asm volatile("cp.async.wait_group %0;" :: "n"(GSTG - 2));
        __syncthreads();

        int j = t + GSTG - 1;
        if (j < GNT)
            g_load_stage(A, Wt, row0, col0, j,
                         sbase + (j % GSTG) * GST_BYTES, tid);
        else
            cp_commit();

        const uint32_t stg = sbase + (t % GSTG) * GST_BYTES;

        #pragma unroll
        for (int ks = 0; ks < 4; ks++) {
            const uint32_t kb = ks * 32;
            uint32_t a0[4], a1[4];
            ldsm_x4(a0, stg + aoff + kb);
            ldsm_x4(a1, stg + aoff + 16 * GROWB + kb);
            #pragma unroll
            for (int np = 0; np < 4; np++) {
                uint32_t bb[4];
                ldsm_x4(bb, stg + boff + np * (16 * GROWB) + kb);
                mma_f16_16x8x16(cf[0][2 * np],     a0, bb[0], bb[1]);
                mma_f16_16x8x16(cf[1][2 * np],     a1, bb[0], bb[1]);
                mma_f16_16x8x16(cf[0][2 * np + 1], a0, bb[2], bb[3]);
                mma_f16_16x8x16(cf[1][2 * np + 1], a1, bb[2], bb[3]);
            }
        }
    }

    #pragma unroll
    for (int mt = 0; mt < 2; mt++) {
        int rbase = row0 + warp_m * 32 + mt * 16 + grp;
        #pragma unroll
        for (int nt = 0; nt < 8; nt++) {
            int col = col0 + warp_n * 64 + nt * 8 + tig * 2;
            float2 b2 = *(const float2*)(bias + col);
            if (HALF_OUT) {
                __half2* o = (__half2*)Cm;
                o[((size_t)rbase * NS + col) / 2] =
                    __floats2half2_rn(cf[mt][nt][0] + b2.x, cf[mt][nt][1] + b2.y);
                o[((size_t)(rbase + 8) * NS + col) / 2] =
                    __floats2half2_rn(cf[mt][nt][2] + b2.x, cf[mt][nt][3] + b2.y);
            } else {
                float* o = (float*)Cm;
                float2 o0, o1;
                o0.x = cf[mt][nt][0] + b2.x;  o0.y = cf[mt][nt][1] + b2.y;
                o1.x = cf[mt][nt][2] + b2.x;  o1.y = cf[mt][nt][3] + b2.y;
                *(float2*)(o + (size_t)rbase * NS + col)       = o0;
                *(float2*)(o + (size_t)(rbase + 8) * NS + col) = o1;
            }
        }
    }
}

// ---------------------------------------------------------------------------
// fp16 tensor-core flash attention (2 CTAs/SM, per-batch launch)
// ---------------------------------------------------------------------------
#define AROWB 144
#define AQB   (128 * AROWB)
#define AKVB  (2 * 128 * AROWB)
#define ASM_BYTES (AQB + 2 * AKVB)     // 92160

template<int CI>
__device__ __forceinline__ void attn_chunk(
    uint32_t qb, uint32_t kb, uint32_t vb,
    int r0, int lane, int grp, int tig, int lo, int hi,
    float (&oc)[8][4], float& m0, float& m1, float& l0, float& l1)
{
    float scr[16][4];
    #pragma unroll
    for (int nt = 0; nt < 16; nt++)
        #pragma unroll
        for (int e = 0; e < 4; e++) scr[nt][e] = 0.f;

    const uint32_t qoff = qb + (r0 + (lane & 15)) * AROWB + ((lane >> 4) & 1) * 16;
    const uint32_t koff = kb + ((lane & 7) + ((lane >> 4) & 1) * 8) * AROWB
                        + ((lane >> 3) & 1) * 16;

    #pragma unroll
    for (int ks = 0; ks < 4; ks++) {
        uint32_t qa[4];
        ldsm_x4(qa, qoff + ks * 32);
        #pragma unroll
        for (int np = 0; np < 8; np++) {
            if (np < lo / 2 || np >= hi / 2) continue;
            uint32_t bb[4];
            ldsm_x4(bb, koff + np * (16 * AROWB) + ks * 32);
            mma_f16_16x8x16(scr[2 * np],     qa, bb[0], bb[1]);
            mma_f16_16x8x16(scr[2 * np + 1], qa, bb[2], bb[3]);
        }
    }
    #pragma unroll
    for (int nt = 0; nt < 16; nt++) {
        if (nt < lo || nt >= hi) continue;
        #pragma unroll
        for (int e = 0; e < 4; e++) scr[nt][e] *= 0.125f;
    }

    const int ra = r0 + grp, rb = ra + 8;
    if (CI == 0) {
        #pragma unroll
        for (int nt = 0; nt < 16; nt++) {
            if (nt < lo || nt >= hi) continue;
            int c = nt * 8 + 2 * tig;
            if (c     < ra) scr[nt][0] = -INFINITY;
            if (c + 1 < ra) scr[nt][1] = -INFINITY;
            if (c     < rb) scr[nt][2] = -INFINITY;
            if (c + 1 < rb) scr[nt][3] = -INFINITY;
        }
    }
    if (CI == 2) {
        #pragma unroll
        for (int nt = 0; nt < 16; nt++) {
            if (nt < lo || nt >= hi) continue;
            int c = nt * 8 + 2 * tig;
            if (c     > ra) scr[nt][0] = -INFINITY;
            if (c + 1 > ra) scr[nt][1] = -INFINITY;
            if (c     > rb) scr[nt][2] = -INFINITY;
            if (c + 1 > rb) scr[nt][3] = -INFINITY;
        }
    }

    float mx0 = -INFINITY, mx1 = -INFINITY;
    #pragma unroll
    for (int nt = 0; nt < 16; nt++) {
        if (nt < lo || nt >= hi) continue;
        mx0 = fmaxf(mx0, fmaxf(scr[nt][0], scr[nt][1]));
        mx1 = fmaxf(mx1, fmaxf(scr[nt][2], scr[nt][3]));
    }
    mx0 = fmaxf(mx0, __shfl_xor_sync(0xffffffffu, mx0, 1));
    mx0 = fmaxf(mx0, __shfl_xor_sync(0xffffffffu, mx0, 2));
    mx1 = fmaxf(mx1, __shfl_xor_sync(0xffffffffu, mx1, 1));
    mx1 = fmaxf(mx1, __shfl_xor_sync(0xffffffffu, mx1, 2));

    float mn0 = fmaxf(m0, mx0), mn1 = fmaxf(m1, mx1);
    float cr0 = __expf(m0 - mn0), cr1 = __expf(m1 - mn1);
    m0 = mn0; m1 = mn1;
    l0 *= cr0; l1 *= cr1;
    #pragma unroll
    for (int nt = 0; nt < 8; nt++) {
        oc[nt][0] *= cr0; oc[nt][1] *= cr0;
        oc[nt][2] *= cr1; oc[nt][3] *= cr1;
    }

    #pragma unroll
    for (int nt = 0; nt < 16; nt++) {
        if (nt < lo || nt >= hi) continue;
        float p0 = __expf(scr[nt][0] - mn0);
        float p1 = __expf(scr[nt][1] - mn0);
        float p2 = __expf(scr[nt][2] - mn1);
        float p3 = __expf(scr[nt][3] - mn1);
        __half2 h01 = __floats2half2_rn(p0, p1);
        __half2 h23 = __floats2half2_rn(p2, p3);
        float2 f01 = __half22float2(h01);
        float2 f23 = __half22float2(h23);
        l0 += f01.x + f01.y;
        l1 += f23.x + f23.y;
        scr[nt][0] = __uint_as_float(*reinterpret_cast<uint32_t*>(&h01));
        scr[nt][1] = __uint_as_float(*reinterpret_cast<uint32_t*>(&h23));
    }

    const uint32_t voffb = vb + (lane & 15) * AROWB + ((lane >> 4) & 1) * 16;
    #pragma unroll
    for (int j = 0; j < 8; j++) {
        if (j < lo / 2 || j >= hi / 2) continue;
        uint32_t pa[4];
        pa[0] = __float_as_uint(scr[2 * j][0]);
        pa[1] = __float_as_uint(scr[2 * j][1]);
        pa[2] = __float_as_uint(scr[2 * j + 1][0]);
        pa[3] = __float_as_uint(scr[2 * j + 1][1]);
        const uint32_t vrow = voffb + j * (16 * AROWB);
        #pragma unroll
        for (int dp = 0; dp < 4; dp++) {
            uint32_t bb[4];
            ldsm_x4_t(bb, vrow + dp * 32);
            mma_f16_16x8x16(oc[2 * dp],     pa, bb[0], bb[1]);
            mma_f16_16x8x16(oc[2 * dp + 1], pa, bb[2], bb[3]);
        }
    }
}

// qkv/att pointers pre-offset to the batch; grid = (NB_, H_, 1)
__global__ __launch_bounds__(256, 2)
void attn_mma_kernel(const __half* __restrict__ qkv,
                     __half* __restrict__ att)
{
    extern __shared__ char sm[];
    const int blk = blockIdx.x, h = blockIdx.y;
    const int tid = threadIdx.x, lane = tid & 31, wid = tid >> 5;
    const int grp = lane >> 2, tig = lane & 3;
    const int r0 = wid * 16;
    const size_t rowbase = (size_t)blk * WIN_;

    const uint32_t qb = smem_u32(sm);
    const uint32_t kv0 = qb + AQB;

    const __half* q = qkv;
    const __half* k = qkv + C_;
    const __half* v = qkv + 2 * C_;

    #pragma unroll
    for (int it = 0; it < 4; it++) {
        int i = tid + it * 256;
        int r = i >> 3, c = i & 7;
        cp_async16(qb + r * AROWB + c * 16,
                   q + (rowbase + r) * NQKV + h * D_ + c * 8);
    }

    auto stage = [&](int ci, int buf) {
        uint32_t kd = kv0 + buf * AKVB;
        uint32_t vd = kd + 128 * AROWB;
        int base = (blk + ci - 1) * WIN_;
        #pragma unroll
        for (int it = 0; it < 8; it++) {
            int i = tid + it * 256;
            int isV = (i >= 1024);
            int ii = i & 1023;
            int r = ii >> 3, c = ii & 7;
            int pos = base + r;
            unsigned sz = (pos >= 0 && pos < L_) ? 16u : 0u;
            int posc = pos < 0 ? 0 : (pos >= L_ ? L_ - 1 : pos);
            const __half* src = (isV ? v : k) + (size_t)posc * NQKV + h * D_ + c * 8;
            uint32_t dst = (isV ? vd : kd) + r * AROWB + c * 16;
            cp_async16z(dst, src, sz);
        }
        cp_commit();
    };

    stage(0, 0);
    stage(1, 1);

    float oc[8][4];
    #pragma unroll
    for (int nt = 0; nt < 8; nt++)
        #pragma unroll
        for (int e = 0; e < 4; e++) oc[nt][e] = 0.f;
    float m0 = -INFINITY, m1 = -INFINITY, l0 = 0.f, l1 = 0.f;

    asm volatile("cp.async.wait_group 1;" ::: "memory");
    __syncthreads();
    attn_chunk<0>(qb, kv0, kv0 + 128 * AROWB, r0, lane, grp, tig,
                  2 * wid, 16, oc, m0, m1, l0, l1);
    __syncthreads();
    stage(2, 0);
    asm volatile("cp.async.wait_group 1;" ::: "memory");
    __syncthreads();
    attn_chunk<1>(qb, kv0 + AKVB, kv0 + AKVB + 128 * AROWB, r0, lane, grp, tig,
                  0, 16, oc, m0, m1, l0, l1);
    asm volatile("cp.async.wait_group 0;" ::: "memory");
    __syncthreads();
    attn_chunk<2>(qb, kv0, kv0 + 128 * AROWB, r0, lane, grp, tig,
                  0, 2 * wid + 2, oc, m0, m1, l0, l1);

    l0 += __shfl_xor_sync(0xffffffffu, l0, 1);
    l0 += __shfl_xor_sync(0xffffffffu, l0, 2);
    l1 += __shfl_xor_sync(0xffffffffu, l1, 1);
    l1 += __shfl_xor_sync(0xffffffffu, l1, 2);
    float i0 = 1.0f / l0, i1 = 1.0f / l1;

    size_t oa = (rowbase + r0 + grp) * C_ + h * D_;
    size_t ob = oa + 8 * C_;
    __half2* o2 = (__half2*)att;
    #pragma unroll
    for (int nt = 0; nt < 8; nt++) {
        o2[(oa + nt * 8 + tig * 2) / 2] =
            __floats2half2_rn(oc[nt][0] * i0, oc[nt][1] * i0);
        o2[(ob + nt * 8 + tig * 2) / 2] =
            __floats2half2_rn(oc[nt][2] * i1, oc[nt][3] * i1);
    }
}

// ---------------------------------------------------------------------------
extern "C" void kernel_launch(void* const* d_in, const int* in_sizes, int n_in,
                              void* d_out, int out_size)
{
    const float* x  = (const float*)d_in[0];
    const float* wq = (const float*)d_in[1];
    const float* bq = (const float*)d_in[2];
    const float* wk = (const float*)d_in[3];
    const float* bk = (const float*)d_in[4];
    const float* wv = (const float*)d_in[5];
    const float* bv = (const float*)d_in[6];
    const float* wo = (const float*)d_in[7];
    const float* bo = (const float*)d_in[8];
    float* out = (float*)d_out;

    __half *qkv, *att, *xh, *wt;
    float *b3;
    cudaGetSymbolAddress((void**)&qkv, g_qkv);
    cudaGetSymbolAddress((void**)&att, g_att);
    cudaGetSymbolAddress((void**)&xh,  g_xh);
    cudaGetSymbolAddress((void**)&wt,  g_wt);
    cudaGetSymbolAddress((void**)&b3,  g_b3);
    __half* wtq = wt;
    __half* wto = wt + 3 * (size_t)C_ * C_;

    static cudaStream_t s1 = nullptr;
    static cudaEvent_t evRoot, evQ0, evWo0;
    if (!s1) {
        cudaStreamCreateWithFlags(&s1, cudaStreamNonBlocking);
        cudaEventCreateWithFlags(&evRoot, cudaEventDisableTiming);
        cudaEventCreateWithFlags(&evQ0,   cudaEventDisableTiming);
        cudaEventCreateWithFlags(&evWo0,  cudaEventDisableTiming);
    }

    cudaFuncSetAttribute(gemm_f16_kernel<true>,
                         cudaFuncAttributeMaxDynamicSharedMemorySize, GSMEM_BYTES);
    cudaFuncSetAttribute(gemm_f16_kernel<false>,
                         cudaFuncAttributeMaxDynamicSharedMemorySize, GSMEM_BYTES);
    cudaFuncSetAttribute(attn_mma_kernel,
                         cudaFuncAttributeMaxDynamicSharedMemorySize, ASM_BYTES);

    // fork side stream
    cudaEventRecord(evRoot, 0);
    cudaStreamWaitEvent(s1, evRoot, 0);

    // s1: wo transpose (off critical path)
    prep_wo_kernel<<<1024, 256, 0, s1>>>(wo, wto);

    // s0: main prep, then QKV batch 0
    prep_main_kernel<<<11268, 256>>>(x, wq, wk, wv, bq, bk, bv, xh, wt, b3);

    dim3 qkvGrid(NQKV / GBN, MHALF / GBM);   // (24, 32)
    gemm_f16_kernel<true><<<qkvGrid, GTHREADS, GSMEM_BYTES>>>(
        xh, wtq, b3, qkv, NQKV);
    cudaEventRecord(evQ0, 0);

    // s0: QKV batch 1
    gemm_f16_kernel<true><<<qkvGrid, GTHREADS, GSMEM_BYTES>>>(
        xh + (size_t)MHALF * C_, wtq, b3, qkv + (size_t)MHALF * NQKV, NQKV);

    // s1: attention batch 0 (after qkv0), then wo batch 0
    cudaStreamWaitEvent(s1, evQ0, 0);
    dim3 aGrid(NB_, H_, 1);
    attn_mma_kernel<<<aGrid, 256, ASM_BYTES, s1>>>(qkv, att);
    dim3 oGrid(C_ / GBN, MHALF / GBM);       // (8, 32)
    gemm_f16_kernel<false><<<oGrid, GTHREADS, GSMEM_BYTES, s1>>>(
        att, wto, bo, out, C_);
    cudaEventRecord(evWo0, s1);

    // s0: attention batch 1, join, wo batch 1
    attn_mma_kernel<<<aGrid, 256, ASM_BYTES>>>(
        qkv + (size_t)MHALF * NQKV, att + (size_t)MHALF * C_);
    cudaStreamWaitEvent(0, evWo0, 0);
    gemm_f16_kernel<false><<<oGrid, GTHREADS, GSMEM_BYTES>>>(
        att + (size_t)MHALF * C_, wto, bo, out + (size_t)MHALF * C_, C_);
}